// round 7
// baseline (speedup 1.0000x reference)
#include <cuda_runtime.h>
#include <cstdint>
#include <cstddef>

#define DEVINL __device__ __forceinline__

// ======================= f32x2 packed helpers (Blackwell FFMA2) =======================
DEVINL unsigned long long pack2(float lo, float hi) {
    unsigned long long d;
    asm("mov.b64 %0, {%1, %2};" : "=l"(d)
        : "r"(__float_as_uint(lo)), "r"(__float_as_uint(hi)));
    return d;
}
DEVINL void unpack2(unsigned long long v, float& lo, float& hi) {
    unsigned int a, b;
    asm("mov.b64 {%0, %1}, %2;" : "=r"(a), "=r"(b) : "l"(v));
    lo = __uint_as_float(a);
    hi = __uint_as_float(b);
}
DEVINL unsigned long long fma2(unsigned long long a, unsigned long long b, unsigned long long c) {
    unsigned long long d;
    asm("fma.rn.f32x2 %0, %1, %2, %3;" : "=l"(d) : "l"(a), "l"(b), "l"(c));
    return d;
}
DEVINL unsigned long long mul2(unsigned long long a, unsigned long long b) {
    unsigned long long d;
    asm("mul.rn.f32x2 %0, %1, %2;" : "=l"(d) : "l"(a), "l"(b));
    return d;
}

// ======================= problem constants =======================
constexpr int B_   = 4;
constexpr int C_   = 256;
constexpr int N_   = 4096;   // H*W
constexpr int DQK  = 32;
constexpr int DV   = 256;

// ======================= scratch (no allocs allowed) =======================
__device__ float g_Q[(size_t)B_ * N_ * DQK];   // [B][N][32]
__device__ float g_K[(size_t)B_ * N_ * DQK];   // [B][N][32]
__device__ float g_V[(size_t)B_ * N_ * DV];    // [B][N][256]

// ======================= projection kernel =======================
constexpr int PT     = 64;
constexpr int MTOT   = 320;
constexpr int CCH    = 64;
constexpr int WSTR   = 324;
constexpr int OSTR   = 321;   // padded output staging stride (floats)
constexpr int PROJ_SMEM = (CCH * PT + CCH * WSTR) * 4;   // 99328 >= PT*OSTR*4=82176

__global__ void __launch_bounds__(256, 2) proj_kernel(
    const float* __restrict__ x,
    const float* __restrict__ Wq, const float* __restrict__ bq,
    const float* __restrict__ Wk, const float* __restrict__ bk,
    const float* __restrict__ Wv, const float* __restrict__ bv)
{
    extern __shared__ __align__(16) char dynsm[];
    float* xs = (float*)dynsm;
    float* Ws = (float*)dynsm + CCH * PT;

    const int t  = threadIdx.x;
    const int b  = blockIdx.y;
    const int n0 = blockIdx.x * PT;
    const int p  = t & 63;
    const int g  = t >> 6;

    unsigned long long A[40];
#pragma unroll
    for (int k = 0; k < 40; k++) A[k] = 0ull;

    for (int c0 = 0; c0 < C_; c0 += CCH) {
        __syncthreads();
#pragma unroll
        for (int k = 0; k < (CCH * PT) / 256; k++) {
            int idx = t + k * 256;
            int cc = idx >> 6, pp = idx & 63;
            xs[idx] = x[((size_t)b * C_ + (c0 + cc)) * N_ + (n0 + pp)];
        }
        for (int idx = t; idx < MTOT * CCH; idx += 256) {
            int m = idx / CCH, cc = idx % CCH;
            int c = c0 + cc;
            float w;
            if (m < 32)       w = Wq[m * C_ + c];
            else if (m < 64)  w = Wk[(m - 32) * C_ + c];
            else              w = Wv[(m - 64) * C_ + c];
            Ws[cc * WSTR + m] = w;
        }
        __syncthreads();

#pragma unroll 4
        for (int cc = 0; cc < CCH; cc++) {
            float xv = xs[cc * 64 + p];
            unsigned long long xx = pack2(xv, xv);
            const ulonglong2* wr = (const ulonglong2*)(Ws + cc * WSTR + g * 80);
#pragma unroll
            for (int k = 0; k < 20; k++) {
                ulonglong2 w4 = wr[k];
                A[2 * k]     = fma2(xx, w4.x, A[2 * k]);
                A[2 * k + 1] = fma2(xx, w4.y, A[2 * k + 1]);
            }
        }
    }

    // ---- stage results into smem (bias added), then write coalesced ----
    __syncthreads();
    float* so = (float*)dynsm;   // [PT][OSTR]
#pragma unroll
    for (int k = 0; k < 40; k++) {
        float v0, v1;
        unpack2(A[k], v0, v1);
        int o = g * 80 + 2 * k;
        float bb0, bb1;
        if (o < 32)       { bb0 = bq[o];       bb1 = bq[o + 1]; }
        else if (o < 64)  { bb0 = bk[o - 32];  bb1 = bk[o - 31]; }
        else              { bb0 = bv[o - 64];  bb1 = bv[o - 63]; }
        so[p * OSTR + o]     = v0 + bb0;
        so[p * OSTR + o + 1] = v1 + bb1;
    }
    __syncthreads();

    // coalesced global writes: consecutive threads -> consecutive m
#pragma unroll
    for (int k = 0; k < (PT * MTOT) / 256; k++) {
        int idx = t + k * 256;
        int pp = idx / MTOT, m = idx % MTOT;
        float val = so[pp * OSTR + m];
        int n = n0 + pp;
        if (m < 32)
            g_Q[((size_t)b * N_ + n) * DQK + m] = val;
        else if (m < 64)
            g_K[((size_t)b * N_ + n) * DQK + (m - 32)] = val;
        else
            g_V[((size_t)b * N_ + n) * DV + (m - 64)] = val;
    }
}

// ======================= flash attention kernel =======================
// CTA: (batch, 64-query-row tile). 256 threads = 8 warps.
// warp w owns rows w*8..w*8+7; lane owns cols lane*8..lane*8+7 (phase B)
// and keys j = kk*32 + lane (phase A).
constexpr int BM = 64, BN = 64;
constexpr uint32_t AV0 = 0;                 // 64KB
constexpr uint32_t AV1 = 65536;             // 64KB
constexpr uint32_t AK0 = 131072;            // 8KB
constexpr uint32_t AK1 = 131072 + 8192;     // 8KB
constexpr uint32_t AQ  = 147456;            // 8KB
constexpr int ATTN_SMEM = 147456 + 8192;    // 155648

DEVINL uint32_t swz(uint32_t off) { return off ^ ((off >> 3) & 0x70u); }

DEVINL void cp16(uint32_t dst, const void* src) {
    asm volatile("cp.async.cg.shared.global [%0], [%1], 16;" :: "r"(dst), "l"(src));
}

__global__ void __launch_bounds__(256, 1) attn_kernel(float* __restrict__ out)
{
    extern __shared__ __align__(16) char dynsm[];
    const uint32_t sb = (uint32_t)__cvta_generic_to_shared(dynsm);
    const int t    = threadIdx.x;
    const int b    = blockIdx.y;
    const int n0   = blockIdx.x * BM;
    const int w    = t >> 5;     // warp: rows w*8..w*8+7
    const int lane = t & 31;     // cols lane*8..+7 / keys kk*32+lane

    const char* qbase = (const char*)(g_Q + ((size_t)b * N_ + n0) * DQK);
    const char* kbase = (const char*)(g_K + (size_t)b * N_ * DQK);
    const char* vbase = (const char*)(g_V + (size_t)b * N_ * DV);

    // ---- prologue: Q tile (8KB, plain) + K/V tile 0 (swizzled) ----
#pragma unroll
    for (int k = 0; k < 2; k++) {
        uint32_t off = (uint32_t)(t + k * 256) * 16;
        cp16(sb + AQ + off, qbase + off);
    }
#pragma unroll
    for (int k = 0; k < 2; k++) {
        uint32_t off = (uint32_t)(t + k * 256) * 16;
        cp16(sb + AK0 + swz(off), kbase + off);
    }
#pragma unroll
    for (int k = 0; k < 16; k++) {
        uint32_t off = (uint32_t)(t + k * 256) * 16;
        cp16(sb + AV0 + swz(off), vbase + off);
    }
    asm volatile("cp.async.commit_group;");

    // softmax state: 8 rows (replicated across the 32 lanes of the warp)
    float m_[8], l_[8];
#pragma unroll
    for (int rr = 0; rr < 8; rr++) { m_[rr] = -1e30f; l_[rr] = 0.f; }

    // O accumulators: 8 rows x 8 cols (4 f32x2 per row)
    unsigned long long O2[8][4];
#pragma unroll
    for (int rr = 0; rr < 8; rr++)
#pragma unroll
        for (int i = 0; i < 4; i++) O2[rr][i] = 0ull;

    // loop-invariant swizzled offsets
    const int xork = lane & 7;                 // K row read perm
    const uint32_t voff0 = swz((uint32_t)(lane * 32));
    const uint32_t voff1 = swz((uint32_t)(lane * 32 + 16));

    const float L2E = 1.4426950408889634f;
    const int NBLK = N_ / BN;   // 64

    for (int blk = 0; blk < NBLK; blk++) {
        const int bi = blk & 1;
        if (blk + 1 < NBLK) {
            const int nb = (blk + 1) & 1;
            const char* kt = kbase + (size_t)(blk + 1) * BN * DQK * 4;
            const char* vt = vbase + (size_t)(blk + 1) * BN * DV * 4;
            const uint32_t kdst = sb + (nb ? AK1 : AK0);
            const uint32_t vdst = sb + (nb ? AV1 : AV0);
#pragma unroll
            for (int k = 0; k < 2; k++) {
                uint32_t off = (uint32_t)(t + k * 256) * 16;
                cp16(kdst + swz(off), kt + off);
            }
#pragma unroll
            for (int k = 0; k < 16; k++) {
                uint32_t off = (uint32_t)(t + k * 256) * 16;
                cp16(vdst + swz(off), vt + off);
            }
            asm volatile("cp.async.commit_group;");
            asm volatile("cp.async.wait_group 1;");
        } else {
            asm volatile("cp.async.wait_group 0;");
        }
        __syncthreads();

        const char* ks = dynsm + (bi ? AK1 : AK0);
        const char* vs = dynsm + (bi ? AV1 : AV0);
        const char* qs = dynsm + AQ;

        // ---- phase A: S[rr][kk], key j = kk*32 + lane ----
        float p_[8][2];
#pragma unroll
        for (int kk = 0; kk < 2; kk++) {
            // hoist this lane's K row into registers (16 f32x2)
            unsigned long long k2[16];
            const char* kr = ks + (kk * 32 + lane) * 128;
#pragma unroll
            for (int i = 0; i < 8; i++) {
                ulonglong2 kv = *(const ulonglong2*)(kr + ((i ^ xork) * 16));
                k2[2 * i] = kv.x; k2[2 * i + 1] = kv.y;
            }
#pragma unroll
            for (int rr = 0; rr < 8; rr++) {
                const ulonglong2* qr = (const ulonglong2*)(qs + (w * 8 + rr) * 128);
                unsigned long long s0 = 0ull, s1 = 0ull;
#pragma unroll
                for (int i = 0; i < 8; i++) {
                    ulonglong2 qv = qr[i];            // broadcast LDS
                    s0 = fma2(qv.x, k2[2 * i], s0);
                    s1 = fma2(qv.y, k2[2 * i + 1], s1);
                }
                float a0, a1, c0, c1;
                unpack2(s0, a0, a1);
                unpack2(s1, c0, c1);
                p_[rr][kk] = (a0 + a1) + (c0 + c1);
            }
        }

        // ---- online softmax (per row, across full warp) ----
        float corr_[8];
#pragma unroll
        for (int rr = 0; rr < 8; rr++) {
            float bmax = fmaxf(p_[rr][0], p_[rr][1]);
#pragma unroll
            for (int d = 16; d >= 1; d >>= 1)
                bmax = fmaxf(bmax, __shfl_xor_sync(0xffffffffu, bmax, d, 32));
            float mn   = fmaxf(m_[rr], bmax);
            float corr = exp2f((m_[rr] - mn) * L2E);
            float p0 = exp2f((p_[rr][0] - mn) * L2E);
            float p1 = exp2f((p_[rr][1] - mn) * L2E);
            p_[rr][0] = p0; p_[rr][1] = p1;
            float ls = p0 + p1;
#pragma unroll
            for (int d = 16; d >= 1; d >>= 1)
                ls += __shfl_xor_sync(0xffffffffu, ls, d, 32);
            l_[rr] = l_[rr] * corr + ls;
            m_[rr] = mn;
            corr_[rr] = corr;
        }
#pragma unroll
        for (int rr = 0; rr < 8; rr++) {
            unsigned long long cc2 = pack2(corr_[rr], corr_[rr]);
#pragma unroll
            for (int i = 0; i < 4; i++) O2[rr][i] = mul2(O2[rr][i], cc2);
        }

        // ---- phase B: O[8][8] += P * V ----
#pragma unroll
        for (int kk = 0; kk < 2; kk++) {
#pragma unroll 4
            for (int jg = 0; jg < 32; jg++) {
                const char* vrow = vs + (kk * 32 + jg) * 1024;
                ulonglong2 u0 = *(const ulonglong2*)(vrow + voff0);
                ulonglong2 u1 = *(const ulonglong2*)(vrow + voff1);
                unsigned long long pp[8];
#pragma unroll
                for (int rr = 0; rr < 8; rr++) {
                    float pj = __shfl_sync(0xffffffffu, p_[rr][kk], jg, 32);
                    pp[rr] = pack2(pj, pj);
                }
#pragma unroll
                for (int rr = 0; rr < 8; rr++) {
                    O2[rr][0] = fma2(pp[rr], u0.x, O2[rr][0]);
                    O2[rr][1] = fma2(pp[rr], u0.y, O2[rr][1]);
                    O2[rr][2] = fma2(pp[rr], u1.x, O2[rr][2]);
                    O2[rr][3] = fma2(pp[rr], u1.y, O2[rr][3]);
                }
            }
        }
        __syncthreads();
    }

    // ---- epilogue: out[b][c][n] = O / l ----
    float* ob = out + (size_t)b * C_ * N_;
#pragma unroll
    for (int rr = 0; rr < 8; rr++) {
        const float inv = 1.f / l_[rr];
        const int n = n0 + w * 8 + rr;
#pragma unroll
        for (int i = 0; i < 4; i++) {
            float v0, v1;
            unpack2(O2[rr][i], v0, v1);
            int c = lane * 8 + 2 * i;
            ob[(size_t)c * N_ + n]       = v0 * inv;
            ob[(size_t)(c + 1) * N_ + n] = v1 * inv;
        }
    }
}

// ======================= launch =======================
extern "C" void kernel_launch(void* const* d_in, const int* in_sizes, int n_in,
                              void* d_out, int out_size)
{
    const float* x  = (const float*)d_in[0];
    const float* Wq = (const float*)d_in[1];
    const float* bq = (const float*)d_in[2];
    const float* Wk = (const float*)d_in[3];
    const float* bk = (const float*)d_in[4];
    const float* Wv = (const float*)d_in[5];
    const float* bv = (const float*)d_in[6];
    float* out = (float*)d_out;

    cudaFuncSetAttribute(proj_kernel, cudaFuncAttributeMaxDynamicSharedMemorySize, PROJ_SMEM);
    cudaFuncSetAttribute(attn_kernel, cudaFuncAttributeMaxDynamicSharedMemorySize, ATTN_SMEM);

    proj_kernel<<<dim3(N_ / PT, B_), 256, PROJ_SMEM>>>(x, Wq, bq, Wk, bk, Wv, bv);
    attn_kernel<<<dim3(N_ / BM, B_), 256, ATTN_SMEM>>>(out);
}

// round 10
// speedup vs baseline: 3.8468x; 3.8468x over previous
#include <cuda_runtime.h>
#include <cstdint>
#include <cstddef>

#define DEVINL __device__ __forceinline__

// ============ f32x2 (proj mainloop) ============
DEVINL unsigned long long pack2(float lo, float hi) {
    unsigned long long d;
    asm("mov.b64 %0, {%1, %2};" : "=l"(d)
        : "r"(__float_as_uint(lo)), "r"(__float_as_uint(hi)));
    return d;
}
DEVINL void unpack2(unsigned long long v, float& lo, float& hi) {
    unsigned int a, b;
    asm("mov.b64 {%0, %1}, %2;" : "=r"(a), "=r"(b) : "l"(v));
    lo = __uint_as_float(a);
    hi = __uint_as_float(b);
}
DEVINL unsigned long long fma2(unsigned long long a, unsigned long long b, unsigned long long c) {
    unsigned long long d;
    asm("fma.rn.f32x2 %0, %1, %2, %3;" : "=l"(d) : "l"(a), "l"(b), "l"(c));
    return d;
}

// ============ fp16 pack/unpack ============
DEVINL uint32_t h2(float f0, float f1) {  // f0 -> low half
    uint32_t r;
    asm("cvt.rn.f16x2.f32 %0, %1, %2;" : "=r"(r) : "f"(f1), "f"(f0));
    return r;
}
DEVINL void h2u(uint32_t w, float& f0, float& f1) {
    asm("{.reg .f16 l, h; mov.b32 {l, h}, %2; cvt.f32.f16 %0, l; cvt.f32.f16 %1, h;}"
        : "=f"(f0), "=f"(f1) : "r"(w));
}

// ============ mma.sync m16n8k16 fp16 -> fp32 ============
DEVINL void mma16816(float* d, const uint32_t* a, const uint32_t* b) {
    asm volatile(
        "mma.sync.aligned.m16n8k16.row.col.f32.f16.f16.f32 "
        "{%0,%1,%2,%3}, {%4,%5,%6,%7}, {%8,%9}, {%0,%1,%2,%3};"
        : "+f"(d[0]), "+f"(d[1]), "+f"(d[2]), "+f"(d[3])
        : "r"(a[0]), "r"(a[1]), "r"(a[2]), "r"(a[3]), "r"(b[0]), "r"(b[1]));
}

DEVINL void cp16(uint32_t dst, const void* src) {
    asm volatile("cp.async.cg.shared.global [%0], [%1], 16;" :: "r"(dst), "l"(src));
}
DEVINL void cp_commit() { asm volatile("cp.async.commit_group;"); }
DEVINL uint32_t smem_u32(const void* p) { return (uint32_t)__cvta_generic_to_shared(p); }

// ============ constants ============
constexpr int B_ = 4;
constexpr int C_ = 256;
constexpr int N_ = 4096;

// ============ scratch: fragment-ordered images ============
// Qf: [b][wt=n/16][ks2][hl2][lane32][reg4] u32  (2KB per wt)   Q pre-scaled by log2(e)
// Kf: per 64-key tile: [nt8][ks2][hl2][lane32][reg2] u32 (8KB)
// Vf: per 64-key tile: [ks4][ct32][lane32][reg2] u32 (32KB), single fp16
__device__ char g_Qf[(size_t)B_ * (N_ / 16) * 2048];
__device__ char g_Kf[(size_t)B_ * 64 * 8192];
__device__ char g_Vf[(size_t)B_ * 64 * 32768];

// ============ projection kernel ============
constexpr int PT   = 64;
constexpr int MTOT = 320;
constexpr int CCH  = 64;
constexpr int WSTR = 324;
constexpr int OSTR = 321;
constexpr int PROJ_SMEM = (CCH * PT + CCH * WSTR) * 4;

__global__ void __launch_bounds__(256, 2) proj_kernel(
    const float* __restrict__ x,
    const float* __restrict__ Wq, const float* __restrict__ bq,
    const float* __restrict__ Wk, const float* __restrict__ bk,
    const float* __restrict__ Wv, const float* __restrict__ bv)
{
    extern __shared__ __align__(16) char dynsm[];
    float* xs = (float*)dynsm;
    float* Ws = (float*)dynsm + CCH * PT;

    const int t  = threadIdx.x;
    const int b  = blockIdx.y;
    const int n0 = blockIdx.x * PT;
    const int p  = t & 63;
    const int g  = t >> 6;

    unsigned long long A[40];
#pragma unroll
    for (int k = 0; k < 40; k++) A[k] = 0ull;

    for (int c0 = 0; c0 < C_; c0 += CCH) {
        __syncthreads();
#pragma unroll
        for (int k = 0; k < (CCH * PT) / 256; k++) {
            int idx = t + k * 256;
            int cc = idx >> 6, pp = idx & 63;
            xs[idx] = x[((size_t)b * C_ + (c0 + cc)) * N_ + (n0 + pp)];
        }
        for (int idx = t; idx < MTOT * CCH; idx += 256) {
            int m = idx / CCH, cc = idx % CCH;
            int c = c0 + cc;
            float w;
            if (m < 32)       w = Wq[m * C_ + c];
            else if (m < 64)  w = Wk[(m - 32) * C_ + c];
            else              w = Wv[(m - 64) * C_ + c];
            Ws[cc * WSTR + m] = w;
        }
        __syncthreads();

#pragma unroll 4
        for (int cc = 0; cc < CCH; cc++) {
            float xv = xs[cc * 64 + p];
            unsigned long long xx = pack2(xv, xv);
            const ulonglong2* wr = (const ulonglong2*)(Ws + cc * WSTR + g * 80);
#pragma unroll
            for (int k = 0; k < 20; k++) {
                ulonglong2 w4 = wr[k];
                A[2 * k]     = fma2(xx, w4.x, A[2 * k]);
                A[2 * k + 1] = fma2(xx, w4.y, A[2 * k + 1]);
            }
        }
    }

    // stage fp32 results (bias added) into so[p][m]
    __syncthreads();
    float* so = (float*)dynsm;   // [PT][OSTR]
#pragma unroll
    for (int k = 0; k < 40; k++) {
        float v0, v1;
        unpack2(A[k], v0, v1);
        int o = g * 80 + 2 * k;
        float bb0, bb1;
        if (o < 32)       { bb0 = bq[o];       bb1 = bq[o + 1]; }
        else if (o < 64)  { bb0 = bk[o - 32];  bb1 = bk[o - 31]; }
        else              { bb0 = bv[o - 64];  bb1 = bv[o - 63]; }
        so[p * OSTR + o]     = v0 + bb0;
        so[p * OSTR + o + 1] = v1 + bb1;
    }
    __syncthreads();

    const float L2E = 1.4426950408889634f;
    char* qf = g_Qf + ((size_t)b * (N_ / 16) + blockIdx.x * 4) * 2048;
    char* kf = g_Kf + ((size_t)b * 64 + blockIdx.x) * 8192;
    char* vf = g_Vf + ((size_t)b * 64 + blockIdx.x) * 32768;

    // ---- Q fragment words (2048), split-fp16, scaled by log2(e) ----
#pragma unroll
    for (int it = 0; it < 8; it++) {
        int w = t + it * 256;
        int wt = w >> 9, rem = w & 511;
        int ks = rem >> 8, hl = (rem >> 7) & 1, lane = (rem >> 2) & 31, reg = rem & 3;
        int r = (lane >> 2) + (reg & 1) * 8;
        int p2 = wt * 16 + r;
        int d = ks * 16 + ((reg >> 1) & 1) * 8 + (lane & 3) * 2;
        float v0 = so[p2 * OSTR + d] * L2E, v1 = so[p2 * OSTR + d + 1] * L2E;
        uint32_t hi = h2(v0, v1);
        uint32_t ow = hi;
        if (hl) { float a0, a1; h2u(hi, a0, a1); ow = h2(v0 - a0, v1 - a1); }
        *(uint32_t*)(qf + (size_t)w * 4) = ow;
    }
    // ---- K fragment words (2048), split-fp16 ----
#pragma unroll
    for (int it = 0; it < 8; it++) {
        int w = t + it * 256;
        int nt = w >> 8, ks = (w >> 7) & 1, hl = (w >> 6) & 1, lane = (w >> 1) & 31, reg = w & 1;
        int j = nt * 8 + (lane >> 2);
        int d = ks * 16 + reg * 8 + (lane & 3) * 2;
        float v0 = so[j * OSTR + 32 + d], v1 = so[j * OSTR + 33 + d];
        uint32_t hi = h2(v0, v1);
        uint32_t ow = hi;
        if (hl) { float a0, a1; h2u(hi, a0, a1); ow = h2(v0 - a0, v1 - a1); }
        *(uint32_t*)(kf + (size_t)w * 4) = ow;
    }
    // ---- V fragment words (8192), single fp16 ----
#pragma unroll
    for (int it = 0; it < 32; it++) {
        int w = t + it * 256;
        int ks = w >> 11, ct = (w >> 6) & 31, lane = (w >> 1) & 31, reg = w & 1;
        int c = ct * 8 + (lane >> 2);
        int j = ks * 16 + reg * 8 + (lane & 3) * 2;
        float v0 = so[j * OSTR + 64 + c];
        float v1 = so[(j + 1) * OSTR + 64 + c];
        *(uint32_t*)(vf + (size_t)w * 4) = h2(v0, v1);
    }
}

// ============ fused flash-attention kernel (HMMA) ============
// CTA: 128 q-rows, 8 warps x 16 rows. grid (32, 4) = 128 CTAs.
constexpr int STAGE = 40960;           // 8KB K + 32KB V
constexpr int ATTN_SMEM = 2 * STAGE;   // 80KB

__global__ void __launch_bounds__(256, 1) attn_kernel(float* __restrict__ out)
{
    extern __shared__ __align__(16) char dynsm[];
    const uint32_t sb = smem_u32(dynsm);
    const int t = threadIdx.x, w = t >> 5, lane = t & 31;
    const int b = blockIdx.y;
    const int g = lane >> 2, t4 = lane & 3;
    const int wt = blockIdx.x * 8 + w;

    // Q fragments (registers for the whole kernel)
    uint32_t qA[2][2][4];
    {
        const char* qf = g_Qf + ((size_t)b * (N_ / 16) + wt) * 2048;
#pragma unroll
        for (int ks = 0; ks < 2; ks++)
#pragma unroll
            for (int hl = 0; hl < 2; hl++) {
                uint4 u = *(const uint4*)(qf + ((ks * 2 + hl) * 32 + lane) * 16);
                qA[ks][hl][0] = u.x; qA[ks][hl][1] = u.y;
                qA[ks][hl][2] = u.z; qA[ks][hl][3] = u.w;
            }
    }

    float O[32][4];
#pragma unroll
    for (int ct = 0; ct < 32; ct++)
#pragma unroll
        for (int i = 0; i < 4; i++) O[ct][i] = 0.f;
    float m0 = -1e30f, m1 = -1e30f, l0 = 0.f, l1 = 0.f;

    const char* kfb = g_Kf + (size_t)b * 64 * 8192;
    const char* vfb = g_Vf + (size_t)b * 64 * 32768;

    auto load_tile = [&](int tile, int st) {
        const char* kf = kfb + (size_t)tile * 8192;
        const char* vf = vfb + (size_t)tile * 32768;
        uint32_t base = sb + st * STAGE;
#pragma unroll
        for (int i = 0; i < 2; i++) {
            uint32_t off = (uint32_t)(t + i * 256) * 16;
            cp16(base + off, kf + off);
        }
#pragma unroll
        for (int i = 0; i < 8; i++) {
            uint32_t off = (uint32_t)(t + i * 256) * 16;
            cp16(base + 8192 + off, vf + off);
        }
        cp_commit();
    };

    load_tile(0, 0);

    for (int tile = 0; tile < 64; tile++) {
        const int st = tile & 1;
        if (tile + 1 < 64) {
            load_tile(tile + 1, st ^ 1);
            asm volatile("cp.async.wait_group 1;" ::: "memory");
        } else {
            asm volatile("cp.async.wait_group 0;" ::: "memory");
        }
        __syncthreads();

        const char* smK = dynsm + st * STAGE;
        const char* smV = smK + 8192;

        // ---- QK^T: S(16x64) in sA, split-fp16 3 products ----
        float sA[8][4];
#pragma unroll
        for (int nt = 0; nt < 8; nt++)
#pragma unroll
            for (int i = 0; i < 4; i++) sA[nt][i] = 0.f;

#pragma unroll
        for (int ks = 0; ks < 2; ks++) {
            uint2 bf[8][2];
#pragma unroll
            for (int nt = 0; nt < 8; nt++)
#pragma unroll
                for (int hb = 0; hb < 2; hb++)
                    bf[nt][hb] = *(const uint2*)(smK + (((nt * 2 + ks) * 2 + hb) * 32 + lane) * 8);
#pragma unroll
            for (int nt = 0; nt < 8; nt++)
                mma16816(sA[nt], qA[ks][0], (const uint32_t*)&bf[nt][0]);
#pragma unroll
            for (int nt = 0; nt < 8; nt++)
                mma16816(sA[nt], qA[ks][0], (const uint32_t*)&bf[nt][1]);
#pragma unroll
            for (int nt = 0; nt < 8; nt++)
                mma16816(sA[nt], qA[ks][1], (const uint32_t*)&bf[nt][0]);
        }

        // ---- online softmax (log2 domain; Q pre-scaled) ----
        float mx0 = sA[0][0], mx1 = sA[0][2];
#pragma unroll
        for (int nt = 0; nt < 8; nt++) {
            mx0 = fmaxf(mx0, fmaxf(sA[nt][0], sA[nt][1]));
            mx1 = fmaxf(mx1, fmaxf(sA[nt][2], sA[nt][3]));
        }
        mx0 = fmaxf(mx0, __shfl_xor_sync(0xffffffffu, mx0, 1, 4));
        mx0 = fmaxf(mx0, __shfl_xor_sync(0xffffffffu, mx0, 2, 4));
        mx1 = fmaxf(mx1, __shfl_xor_sync(0xffffffffu, mx1, 1, 4));
        mx1 = fmaxf(mx1, __shfl_xor_sync(0xffffffffu, mx1, 2, 4));
        float mn0 = fmaxf(m0, mx0), mn1 = fmaxf(m1, mx1);
        float corr0 = exp2f(m0 - mn0), corr1 = exp2f(m1 - mn1);
        m0 = mn0; m1 = mn1;

        uint32_t pf[8][2];
        float ls0 = 0.f, ls1 = 0.f;
#pragma unroll
        for (int nt = 0; nt < 8; nt++) {
            float p0 = exp2f(sA[nt][0] - mn0);
            float p1 = exp2f(sA[nt][1] - mn0);
            float p2 = exp2f(sA[nt][2] - mn1);
            float p3 = exp2f(sA[nt][3] - mn1);
            ls0 += p0 + p1; ls1 += p2 + p3;
            pf[nt][0] = h2(p0, p1);
            pf[nt][1] = h2(p2, p3);
        }
        ls0 += __shfl_xor_sync(0xffffffffu, ls0, 1, 4);
        ls0 += __shfl_xor_sync(0xffffffffu, ls0, 2, 4);
        ls1 += __shfl_xor_sync(0xffffffffu, ls1, 1, 4);
        ls1 += __shfl_xor_sync(0xffffffffu, ls1, 2, 4);
        l0 = l0 * corr0 + ls0;
        l1 = l1 * corr1 + ls1;

#pragma unroll
        for (int ct = 0; ct < 32; ct++) {
            O[ct][0] *= corr0; O[ct][1] *= corr0;
            O[ct][2] *= corr1; O[ct][3] *= corr1;
        }

        // ---- P V: O(16x256) += P(16x64) V(64x256), fp16 ----
#pragma unroll
        for (int ks = 0; ks < 4; ks++) {
            uint32_t a[4] = { pf[2 * ks][0], pf[2 * ks][1], pf[2 * ks + 1][0], pf[2 * ks + 1][1] };
#pragma unroll
            for (int ct = 0; ct < 32; ct++) {
                uint2 vb = *(const uint2*)(smV + ((ks * 32 + ct) * 32 + lane) * 8);
                mma16816(O[ct], a, (const uint32_t*)&vb);
            }
        }
        __syncthreads();
    }

    // ---- epilogue ----
    const float inv0 = 1.f / l0, inv1 = 1.f / l1;
    const int nr0 = blockIdx.x * 128 + w * 16 + g;
    const int nr1 = nr0 + 8;
    float* ob = out + (size_t)b * C_ * N_;
#pragma unroll
    for (int ct = 0; ct < 32; ct++) {
        int c = ct * 8 + t4 * 2;
        ob[(size_t)c * N_ + nr0]       = O[ct][0] * inv0;
        ob[(size_t)(c + 1) * N_ + nr0] = O[ct][1] * inv0;
        ob[(size_t)c * N_ + nr1]       = O[ct][2] * inv1;
        ob[(size_t)(c + 1) * N_ + nr1] = O[ct][3] * inv1;
    }
}

// ============ launch ============
extern "C" void kernel_launch(void* const* d_in, const int* in_sizes, int n_in,
                              void* d_out, int out_size)
{
    const float* x  = (const float*)d_in[0];
    const float* Wq = (const float*)d_in[1];
    const float* bq = (const float*)d_in[2];
    const float* Wk = (const float*)d_in[3];
    const float* bk = (const float*)d_in[4];
    const float* Wv = (const float*)d_in[5];
    const float* bv = (const float*)d_in[6];
    float* out = (float*)d_out;

    cudaFuncSetAttribute(proj_kernel, cudaFuncAttributeMaxDynamicSharedMemorySize, PROJ_SMEM);
    cudaFuncSetAttribute(attn_kernel, cudaFuncAttributeMaxDynamicSharedMemorySize, ATTN_SMEM);

    proj_kernel<<<dim3(N_ / PT, B_), 256, PROJ_SMEM>>>(x, Wq, bq, Wk, bk, Wv, bv);
    attn_kernel<<<dim3(N_ / 128, B_), 256, ATTN_SMEM>>>(out);
}

// round 12
// speedup vs baseline: 6.3126x; 1.6410x over previous
#include <cuda_runtime.h>
#include <cstdint>
#include <cstddef>

#define DEVINL __device__ __forceinline__

// ============ fp16 pack/unpack ============
DEVINL uint32_t h2(float f0, float f1) {  // f0 -> low half
    uint32_t r;
    asm("cvt.rn.f16x2.f32 %0, %1, %2;" : "=r"(r) : "f"(f1), "f"(f0));
    return r;
}
DEVINL void h2u(uint32_t w, float& f0, float& f1) {
    asm("{.reg .f16 l, h; mov.b32 {l, h}, %2; cvt.f32.f16 %0, l; cvt.f32.f16 %1, h;}"
        : "=f"(f0), "=f"(f1) : "r"(w));
}
// split helper: word for (v0,v1); hl=0 -> hi, hl=1 -> lo
DEVINL uint32_t split_word(float v0, float v1, int hl) {
    uint32_t hi = h2(v0, v1);
    if (!hl) return hi;
    float a0, a1;
    h2u(hi, a0, a1);
    return h2(v0 - a0, v1 - a1);
}

// ============ mma.sync m16n8k16 fp16 -> fp32 ============
DEVINL void mma16816(float* d, const uint32_t* a, const uint32_t* b) {
    asm volatile(
        "mma.sync.aligned.m16n8k16.row.col.f32.f16.f16.f32 "
        "{%0,%1,%2,%3}, {%4,%5,%6,%7}, {%8,%9}, {%0,%1,%2,%3};"
        : "+f"(d[0]), "+f"(d[1]), "+f"(d[2]), "+f"(d[3])
        : "r"(a[0]), "r"(a[1]), "r"(a[2]), "r"(a[3]), "r"(b[0]), "r"(b[1]));
}

DEVINL void cp16(uint32_t dst, const void* src) {
    asm volatile("cp.async.cg.shared.global [%0], [%1], 16;" :: "r"(dst), "l"(src));
}
DEVINL void cp_commit() { asm volatile("cp.async.commit_group;"); }
DEVINL uint32_t smem_u32(const void* p) { return (uint32_t)__cvta_generic_to_shared(p); }

// ============ constants ============
constexpr int B_ = 4;
constexpr int C_ = 256;
constexpr int N_ = 4096;
constexpr int OSTR = 321;

// ============ scratch ============
// Qf: [b][wt=n/16][ks2][hl2][lane32][reg4] u32 (2KB/wt), pre-scaled by log2(e)
// Kf: per 64-key tile: [nt8][ks2][hl2][lane32][reg2] u32 (8KB)
// Vf: per 64-key tile: [ks4][ct32][lane32][reg2] u32 (32KB), single fp16
__device__ char g_Qf[(size_t)B_ * (N_ / 16) * 2048];
__device__ char g_Kf[(size_t)B_ * 64 * 8192];
__device__ char g_Vf[(size_t)B_ * 64 * 32768];
// Wf: W fragment image (B-operand): [chunk4][half2][nblk20][ks4][hl2][lane32][reg2] u32
__device__ uint32_t g_Wf[81920];
// Xf: x fragment image (A-operand): [b][tile64][chunk4][strip4][ks4][hl2][lane32][reg4] u32
__device__ uint32_t g_Xf[(size_t)B_ * 64 * 16384];

// ============ wprep: W -> fragment-ordered split-fp16 ============
__global__ void wprep_kernel(const float* __restrict__ Wq,
                             const float* __restrict__ Wk,
                             const float* __restrict__ Wv)
{
    int wi = blockIdx.x * 256 + threadIdx.x;   // 81920 words
    int reg  = wi & 1;
    int lane = (wi >> 1) & 31;
    int hl   = (wi >> 6) & 1;
    int ks   = (wi >> 7) & 3;
    int nblk = (wi >> 9) % 20;
    int tmp  = (wi >> 9) / 20;
    int half = tmp & 1;
    int chunk = tmp >> 1;
    int m = half * 160 + nblk * 8 + (lane >> 2);
    int c = chunk * 64 + ks * 16 + reg * 8 + (lane & 3) * 2;
    const float* src;
    if (m < 32)       src = Wq + (size_t)m * C_ + c;
    else if (m < 64)  src = Wk + (size_t)(m - 32) * C_ + c;
    else              src = Wv + (size_t)(m - 64) * C_ + c;
    g_Wf[wi] = split_word(src[0], src[1], hl);
}

// ============ xprep: x -> fragment-ordered split-fp16 (smem transpose) ============
constexpr int XSTR = 68;                       // padded floats per c-row
constexpr int XP_SMEM = 256 * XSTR * 4;        // 69632

__global__ void __launch_bounds__(256, 1) xprep_kernel(const float* __restrict__ x)
{
    extern __shared__ __align__(16) char dynsm[];
    float* xs = (float*)dynsm;                 // [256 c][XSTR]
    const int t = threadIdx.x;
    const int tile = blockIdx.x, b = blockIdx.y;

    // load x[256 c][64 px] coalesced
#pragma unroll
    for (int it = 0; it < 16; it++) {
        int idx = t + it * 256;
        int c = idx >> 4, f4 = idx & 15;
        float4 u = *(const float4*)(x + ((size_t)b * C_ + c) * N_ + tile * 64 + f4 * 4);
        *(float4*)(xs + c * XSTR + f4 * 4) = u;
    }
    __syncthreads();

    uint32_t* dst = g_Xf + ((size_t)b * 64 + tile) * 16384;
#pragma unroll
    for (int it = 0; it < 64; it++) {
        int idx = t + it * 256;
        int reg   = idx & 3;
        int lane  = (idx >> 2) & 31;
        int hl    = (idx >> 7) & 1;
        int ks    = (idx >> 8) & 3;
        int strip = (idx >> 10) & 3;
        int chunk = idx >> 12;
        int px = strip * 16 + (lane >> 2) + (reg & 1) * 8;
        int c  = chunk * 64 + ks * 16 + ((reg >> 1) & 1) * 8 + (lane & 3) * 2;
        float v0 = xs[c * XSTR + px];
        float v1 = xs[(c + 1) * XSTR + px];
        dst[idx] = split_word(v0, v1, hl);
    }
}

// ============ proj: out[64px x 320m] = x W^T via HMMA, pack Qf/Kf/Vf ============
// stage = 81920 (W chunk) + 16384 (X chunk) = 98304; double-buffered
constexpr int PJ_STAGE = 98304;
constexpr int PJ_SMEM  = 2 * PJ_STAGE;         // 196608

__global__ void __launch_bounds__(256, 1) proj_kernel(
    const float* __restrict__ bq, const float* __restrict__ bk,
    const float* __restrict__ bv)
{
    extern __shared__ __align__(16) char dynsm[];
    const uint32_t sb = smem_u32(dynsm);
    const int t = threadIdx.x, w = t >> 5, lane = t & 31;
    const int g = lane >> 2, t4 = lane & 3;
    const int strip = w & 3, half = w >> 2;
    const int tile = blockIdx.x, b = blockIdx.y;

    const char* wfb = (const char*)g_Wf;                                  // [chunk][81920]
    const char* xfb = (const char*)(g_Xf + ((size_t)b * 64 + tile) * 16384); // [chunk][16384]

    auto load_chunk = [&](int c, int st) {
        uint32_t base = sb + st * PJ_STAGE;
        const char* ws = wfb + (size_t)c * 81920;
#pragma unroll
        for (int i = 0; i < 20; i++) {
            uint32_t off = (uint32_t)(t + i * 256) * 16;
            cp16(base + off, ws + off);
        }
        const char* xsrc = xfb + (size_t)c * 16384;
#pragma unroll
        for (int i = 0; i < 4; i++) {
            uint32_t off = (uint32_t)(t + i * 256) * 16;
            cp16(base + 81920 + off, xsrc + off);
        }
        cp_commit();
    };

    float acc[20][4];
#pragma unroll
    for (int nb = 0; nb < 20; nb++)
#pragma unroll
        for (int i = 0; i < 4; i++) acc[nb][i] = 0.f;

    load_chunk(0, 0);

    for (int c = 0; c < 4; c++) {
        const int st = c & 1;
        if (c + 1 < 4) {
            load_chunk(c + 1, st ^ 1);
            asm volatile("cp.async.wait_group 1;" ::: "memory");
        } else {
            asm volatile("cp.async.wait_group 0;" ::: "memory");
        }
        __syncthreads();

        const char* smW = dynsm + st * PJ_STAGE;
        const char* smX = smW + 81920;

#pragma unroll
        for (int ks = 0; ks < 4; ks++) {
            uint32_t ah[4], al[4];
            {
                uint4 u = *(const uint4*)(smX + (((strip * 4 + ks) * 2 + 0) * 32 + lane) * 16);
                ah[0] = u.x; ah[1] = u.y; ah[2] = u.z; ah[3] = u.w;
                uint4 v = *(const uint4*)(smX + (((strip * 4 + ks) * 2 + 1) * 32 + lane) * 16);
                al[0] = v.x; al[1] = v.y; al[2] = v.z; al[3] = v.w;
            }
#pragma unroll
            for (int nb = 0; nb < 20; nb++) {
                const char* wbase = smW + ((((half * 20 + nb) * 4 + ks) * 2) * 32 + lane) * 8;
                uint2 bh = *(const uint2*)wbase;
                uint2 bl = *(const uint2*)(wbase + 256);
                mma16816(acc[nb], ah, (const uint32_t*)&bh);
                mma16816(acc[nb], al, (const uint32_t*)&bh);
                mma16816(acc[nb], ah, (const uint32_t*)&bl);
            }
        }
        __syncthreads();
    }

    // ---- stage acc into so[px][OSTR] (fp32) ----
    float* so = (float*)dynsm;    // 64*321*4 = 82176 <= stage0 (chunk2, no longer read)
#pragma unroll
    for (int nb = 0; nb < 20; nb++) {
        int m = half * 160 + nb * 8 + t4 * 2;
        int px0 = strip * 16 + g, px1 = px0 + 8;
        so[px0 * OSTR + m]     = acc[nb][0];
        so[px0 * OSTR + m + 1] = acc[nb][1];
        so[px1 * OSTR + m]     = acc[nb][2];
        so[px1 * OSTR + m + 1] = acc[nb][3];
    }
    __syncthreads();

    // ---- fragment pack (round-10 verified layout), bias added here ----
    const float L2E = 1.4426950408889634f;
    char* qf = g_Qf + ((size_t)b * (N_ / 16) + tile * 4) * 2048;
    char* kf = g_Kf + ((size_t)b * 64 + tile) * 8192;
    char* vf = g_Vf + ((size_t)b * 64 + tile) * 32768;

    // Q (2048 words), pre-scaled by log2(e)
#pragma unroll
    for (int it = 0; it < 8; it++) {
        int w2 = t + it * 256;
        int wt = w2 >> 9, rem = w2 & 511;
        int ks = rem >> 8, hl = (rem >> 7) & 1, lane2 = (rem >> 2) & 31, reg = rem & 3;
        int r = (lane2 >> 2) + (reg & 1) * 8;
        int p2 = wt * 16 + r;
        int d = ks * 16 + ((reg >> 1) & 1) * 8 + (lane2 & 3) * 2;
        float v0 = (so[p2 * OSTR + d] + bq[d]) * L2E;
        float v1 = (so[p2 * OSTR + d + 1] + bq[d + 1]) * L2E;
        *(uint32_t*)(qf + (size_t)w2 * 4) = split_word(v0, v1, hl);
    }
    // K (2048 words)
#pragma unroll
    for (int it = 0; it < 8; it++) {
        int w2 = t + it * 256;
        int nt = w2 >> 8, ks = (w2 >> 7) & 1, hl = (w2 >> 6) & 1, lane2 = (w2 >> 1) & 31, reg = w2 & 1;
        int j = nt * 8 + (lane2 >> 2);
        int d = ks * 16 + reg * 8 + (lane2 & 3) * 2;
        float v0 = so[j * OSTR + 32 + d] + bk[d];
        float v1 = so[j * OSTR + 33 + d] + bk[d + 1];
        *(uint32_t*)(kf + (size_t)w2 * 4) = split_word(v0, v1, hl);
    }
    // V (8192 words), single fp16
#pragma unroll
    for (int it = 0; it < 32; it++) {
        int w2 = t + it * 256;
        int ks = w2 >> 11, ct = (w2 >> 6) & 31, lane2 = (w2 >> 1) & 31, reg = w2 & 1;
        int c = ct * 8 + (lane2 >> 2);
        int j = ks * 16 + reg * 8 + (lane2 & 3) * 2;
        float bb = bv[c];
        float v0 = so[j * OSTR + 64 + c] + bb;
        float v1 = so[(j + 1) * OSTR + 64 + c] + bb;
        *(uint32_t*)(vf + (size_t)w2 * 4) = h2(v0, v1);
    }
}

// ============ fused flash-attention kernel (HMMA, unchanged from round 10) ============
constexpr int STAGE = 40960;           // 8KB K + 32KB V
constexpr int ATTN_SMEM = 2 * STAGE;   // 80KB

__global__ void __launch_bounds__(256, 1) attn_kernel(float* __restrict__ out)
{
    extern __shared__ __align__(16) char dynsm[];
    const uint32_t sb = smem_u32(dynsm);
    const int t = threadIdx.x, w = t >> 5, lane = t & 31;
    const int b = blockIdx.y;
    const int g = lane >> 2, t4 = lane & 3;
    const int wt = blockIdx.x * 8 + w;

    uint32_t qA[2][2][4];
    {
        const char* qf = g_Qf + ((size_t)b * (N_ / 16) + wt) * 2048;
#pragma unroll
        for (int ks = 0; ks < 2; ks++)
#pragma unroll
            for (int hl = 0; hl < 2; hl++) {
                uint4 u = *(const uint4*)(qf + ((ks * 2 + hl) * 32 + lane) * 16);
                qA[ks][hl][0] = u.x; qA[ks][hl][1] = u.y;
                qA[ks][hl][2] = u.z; qA[ks][hl][3] = u.w;
            }
    }

    float O[32][4];
#pragma unroll
    for (int ct = 0; ct < 32; ct++)
#pragma unroll
        for (int i = 0; i < 4; i++) O[ct][i] = 0.f;
    float m0 = -1e30f, m1 = -1e30f, l0 = 0.f, l1 = 0.f;

    const char* kfb = g_Kf + (size_t)b * 64 * 8192;
    const char* vfb = g_Vf + (size_t)b * 64 * 32768;

    auto load_tile = [&](int tile, int st) {
        const char* kf = kfb + (size_t)tile * 8192;
        const char* vf = vfb + (size_t)tile * 32768;
        uint32_t base = sb + st * STAGE;
#pragma unroll
        for (int i = 0; i < 2; i++) {
            uint32_t off = (uint32_t)(t + i * 256) * 16;
            cp16(base + off, kf + off);
        }
#pragma unroll
        for (int i = 0; i < 8; i++) {
            uint32_t off = (uint32_t)(t + i * 256) * 16;
            cp16(base + 8192 + off, vf + off);
        }
        cp_commit();
    };

    load_tile(0, 0);

    for (int tile = 0; tile < 64; tile++) {
        const int st = tile & 1;
        if (tile + 1 < 64) {
            load_tile(tile + 1, st ^ 1);
            asm volatile("cp.async.wait_group 1;" ::: "memory");
        } else {
            asm volatile("cp.async.wait_group 0;" ::: "memory");
        }
        __syncthreads();

        const char* smK = dynsm + st * STAGE;
        const char* smV = smK + 8192;

        float sA[8][4];
#pragma unroll
        for (int nt = 0; nt < 8; nt++)
#pragma unroll
            for (int i = 0; i < 4; i++) sA[nt][i] = 0.f;

#pragma unroll
        for (int ks = 0; ks < 2; ks++) {
            uint2 bf[8][2];
#pragma unroll
            for (int nt = 0; nt < 8; nt++)
#pragma unroll
                for (int hb = 0; hb < 2; hb++)
                    bf[nt][hb] = *(const uint2*)(smK + (((nt * 2 + ks) * 2 + hb) * 32 + lane) * 8);
#pragma unroll
            for (int nt = 0; nt < 8; nt++)
                mma16816(sA[nt], qA[ks][0], (const uint32_t*)&bf[nt][0]);
#pragma unroll
            for (int nt = 0; nt < 8; nt++)
                mma16816(sA[nt], qA[ks][0], (const uint32_t*)&bf[nt][1]);
#pragma unroll
            for (int nt = 0; nt < 8; nt++)
                mma16816(sA[nt], qA[ks][1], (const uint32_t*)&bf[nt][0]);
        }

        float mx0 = sA[0][0], mx1 = sA[0][2];
#pragma unroll
        for (int nt = 0; nt < 8; nt++) {
            mx0 = fmaxf(mx0, fmaxf(sA[nt][0], sA[nt][1]));
            mx1 = fmaxf(mx1, fmaxf(sA[nt][2], sA[nt][3]));
        }
        mx0 = fmaxf(mx0, __shfl_xor_sync(0xffffffffu, mx0, 1, 4));
        mx0 = fmaxf(mx0, __shfl_xor_sync(0xffffffffu, mx0, 2, 4));
        mx1 = fmaxf(mx1, __shfl_xor_sync(0xffffffffu, mx1, 1, 4));
        mx1 = fmaxf(mx1, __shfl_xor_sync(0xffffffffu, mx1, 2, 4));
        float mn0 = fmaxf(m0, mx0), mn1 = fmaxf(m1, mx1);
        float corr0 = exp2f(m0 - mn0), corr1 = exp2f(m1 - mn1);
        m0 = mn0; m1 = mn1;

        uint32_t pf[8][2];
        float ls0 = 0.f, ls1 = 0.f;
#pragma unroll
        for (int nt = 0; nt < 8; nt++) {
            float p0 = exp2f(sA[nt][0] - mn0);
            float p1 = exp2f(sA[nt][1] - mn0);
            float p2 = exp2f(sA[nt][2] - mn1);
            float p3 = exp2f(sA[nt][3] - mn1);
            ls0 += p0 + p1; ls1 += p2 + p3;
            pf[nt][0] = h2(p0, p1);
            pf[nt][1] = h2(p2, p3);
        }
        ls0 += __shfl_xor_sync(0xffffffffu, ls0, 1, 4);
        ls0 += __shfl_xor_sync(0xffffffffu, ls0, 2, 4);
        ls1 += __shfl_xor_sync(0xffffffffu, ls1, 1, 4);
        ls1 += __shfl_xor_sync(0xffffffffu, ls1, 2, 4);
        l0 = l0 * corr0 + ls0;
        l1 = l1 * corr1 + ls1;

#pragma unroll
        for (int ct = 0; ct < 32; ct++) {
            O[ct][0] *= corr0; O[ct][1] *= corr0;
            O[ct][2] *= corr1; O[ct][3] *= corr1;
        }

#pragma unroll
        for (int ks = 0; ks < 4; ks++) {
            uint32_t a[4] = { pf[2 * ks][0], pf[2 * ks][1], pf[2 * ks + 1][0], pf[2 * ks + 1][1] };
#pragma unroll
            for (int ct = 0; ct < 32; ct++) {
                uint2 vb = *(const uint2*)(smV + ((ks * 32 + ct) * 32 + lane) * 8);
                mma16816(O[ct], a, (const uint32_t*)&vb);
            }
        }
        __syncthreads();
    }

    const float inv0 = 1.f / l0, inv1 = 1.f / l1;
    const int nr0 = blockIdx.x * 128 + w * 16 + g;
    const int nr1 = nr0 + 8;
    float* ob = out + (size_t)b * C_ * N_;
#pragma unroll
    for (int ct = 0; ct < 32; ct++) {
        int c = ct * 8 + t4 * 2;
        ob[(size_t)c * N_ + nr0]       = O[ct][0] * inv0;
        ob[(size_t)(c + 1) * N_ + nr0] = O[ct][1] * inv0;
        ob[(size_t)c * N_ + nr1]       = O[ct][2] * inv1;
        ob[(size_t)(c + 1) * N_ + nr1] = O[ct][3] * inv1;
    }
}

// ============ launch ============
extern "C" void kernel_launch(void* const* d_in, const int* in_sizes, int n_in,
                              void* d_out, int out_size)
{
    const float* x  = (const float*)d_in[0];
    const float* Wq = (const float*)d_in[1];
    const float* bq = (const float*)d_in[2];
    const float* Wk = (const float*)d_in[3];
    const float* bk = (const float*)d_in[4];
    const float* Wv = (const float*)d_in[5];
    const float* bv = (const float*)d_in[6];
    float* out = (float*)d_out;

    cudaFuncSetAttribute(xprep_kernel, cudaFuncAttributeMaxDynamicSharedMemorySize, XP_SMEM);
    cudaFuncSetAttribute(proj_kernel,  cudaFuncAttributeMaxDynamicSharedMemorySize, PJ_SMEM);
    cudaFuncSetAttribute(attn_kernel,  cudaFuncAttributeMaxDynamicSharedMemorySize, ATTN_SMEM);

    wprep_kernel<<<320, 256>>>(Wq, Wk, Wv);
    xprep_kernel<<<dim3(64, B_), 256, XP_SMEM>>>(x);
    proj_kernel<<<dim3(64, B_), 256, PJ_SMEM>>>(bq, bk, bv);
    attn_kernel<<<dim3(N_ / 128, B_), 256, ATTN_SMEM>>>(out);
}

// round 13
// speedup vs baseline: 6.4300x; 1.0186x over previous
#include <cuda_runtime.h>
#include <cstdint>
#include <cstddef>

#define DEVINL __device__ __forceinline__

// ============ fp16 pack/unpack ============
DEVINL uint32_t h2(float f0, float f1) {  // f0 -> low half
    uint32_t r;
    asm("cvt.rn.f16x2.f32 %0, %1, %2;" : "=r"(r) : "f"(f1), "f"(f0));
    return r;
}
DEVINL void h2u(uint32_t w, float& f0, float& f1) {
    asm("{.reg .f16 l, h; mov.b32 {l, h}, %2; cvt.f32.f16 %0, l; cvt.f32.f16 %1, h;}"
        : "=f"(f0), "=f"(f1) : "r"(w));
}
DEVINL uint32_t split_word(float v0, float v1, int hl) {
    uint32_t hi = h2(v0, v1);
    if (!hl) return hi;
    float a0, a1;
    h2u(hi, a0, a1);
    return h2(v0 - a0, v1 - a1);
}
DEVINL uint32_t hmul2(uint32_t a, uint32_t b) {
    uint32_t r;
    asm("mul.f16x2 %0, %1, %2;" : "=r"(r) : "r"(a), "r"(b));
    return r;
}
DEVINL float ex2a(float x) {
    float y;
    asm("ex2.approx.ftz.f32 %0, %1;" : "=f"(y) : "f"(x));
    return y;
}

// ============ mma.sync m16n8k16 fp16 -> fp32 ============
DEVINL void mma16816(float* d, const uint32_t* a, const uint32_t* b) {
    asm volatile(
        "mma.sync.aligned.m16n8k16.row.col.f32.f16.f16.f32 "
        "{%0,%1,%2,%3}, {%4,%5,%6,%7}, {%8,%9}, {%0,%1,%2,%3};"
        : "+f"(d[0]), "+f"(d[1]), "+f"(d[2]), "+f"(d[3])
        : "r"(a[0]), "r"(a[1]), "r"(a[2]), "r"(a[3]), "r"(b[0]), "r"(b[1]));
}

DEVINL void cp16(uint32_t dst, const void* src) {
    asm volatile("cp.async.cg.shared.global [%0], [%1], 16;" :: "r"(dst), "l"(src));
}
DEVINL void cp_commit() { asm volatile("cp.async.commit_group;"); }
DEVINL uint32_t smem_u32(const void* p) { return (uint32_t)__cvta_generic_to_shared(p); }

// ============ constants ============
constexpr int B_ = 4;
constexpr int C_ = 256;
constexpr int N_ = 4096;
constexpr int OSTR = 321;

// ============ scratch ============
__device__ char g_Qf[(size_t)B_ * (N_ / 16) * 2048];
__device__ char g_Kf[(size_t)B_ * 64 * 8192];
__device__ char g_Vf[(size_t)B_ * 64 * 32768];
__device__ uint32_t g_Wf[81920];
__device__ uint32_t g_Xf[(size_t)B_ * 64 * 16384];

// ============ wprep ============
__global__ void wprep_kernel(const float* __restrict__ Wq,
                             const float* __restrict__ Wk,
                             const float* __restrict__ Wv)
{
    int wi = blockIdx.x * 256 + threadIdx.x;
    int reg  = wi & 1;
    int lane = (wi >> 1) & 31;
    int hl   = (wi >> 6) & 1;
    int ks   = (wi >> 7) & 3;
    int nblk = (wi >> 9) % 20;
    int tmp  = (wi >> 9) / 20;
    int half = tmp & 1;
    int chunk = tmp >> 1;
    int m = half * 160 + nblk * 8 + (lane >> 2);
    int c = chunk * 64 + ks * 16 + reg * 8 + (lane & 3) * 2;
    const float* src;
    if (m < 32)       src = Wq + (size_t)m * C_ + c;
    else if (m < 64)  src = Wk + (size_t)(m - 32) * C_ + c;
    else              src = Wv + (size_t)(m - 64) * C_ + c;
    g_Wf[wi] = split_word(src[0], src[1], hl);
}

// ============ xprep ============
constexpr int XSTR = 68;
constexpr int XP_SMEM = 256 * XSTR * 4;

__global__ void __launch_bounds__(256, 1) xprep_kernel(const float* __restrict__ x)
{
    extern __shared__ __align__(16) char dynsm[];
    float* xs = (float*)dynsm;
    const int t = threadIdx.x;
    const int tile = blockIdx.x, b = blockIdx.y;

#pragma unroll
    for (int it = 0; it < 16; it++) {
        int idx = t + it * 256;
        int c = idx >> 4, f4 = idx & 15;
        float4 u = *(const float4*)(x + ((size_t)b * C_ + c) * N_ + tile * 64 + f4 * 4);
        *(float4*)(xs + c * XSTR + f4 * 4) = u;
    }
    __syncthreads();

    uint32_t* dst = g_Xf + ((size_t)b * 64 + tile) * 16384;
#pragma unroll
    for (int it = 0; it < 64; it++) {
        int idx = t + it * 256;
        int reg   = idx & 3;
        int lane  = (idx >> 2) & 31;
        int hl    = (idx >> 7) & 1;
        int ks    = (idx >> 8) & 3;
        int strip = (idx >> 10) & 3;
        int chunk = idx >> 12;
        int px = strip * 16 + (lane >> 2) + (reg & 1) * 8;
        int c  = chunk * 64 + ks * 16 + ((reg >> 1) & 1) * 8 + (lane & 3) * 2;
        float v0 = xs[c * XSTR + px];
        float v1 = xs[(c + 1) * XSTR + px];
        dst[idx] = split_word(v0, v1, hl);
    }
}

// ============ proj ============
constexpr int PJ_STAGE = 98304;
constexpr int PJ_SMEM  = 2 * PJ_STAGE;

__global__ void __launch_bounds__(256, 1) proj_kernel(
    const float* __restrict__ bq, const float* __restrict__ bk,
    const float* __restrict__ bv)
{
    extern __shared__ __align__(16) char dynsm[];
    const uint32_t sb = smem_u32(dynsm);
    const int t = threadIdx.x, w = t >> 5, lane = t & 31;
    const int g = lane >> 2, t4 = lane & 3;
    const int strip = w & 3, half = w >> 2;
    const int tile = blockIdx.x, b = blockIdx.y;

    const char* wfb = (const char*)g_Wf;
    const char* xfb = (const char*)(g_Xf + ((size_t)b * 64 + tile) * 16384);

    auto load_chunk = [&](int c, int st) {
        uint32_t base = sb + st * PJ_STAGE;
        const char* ws = wfb + (size_t)c * 81920;
#pragma unroll
        for (int i = 0; i < 20; i++) {
            uint32_t off = (uint32_t)(t + i * 256) * 16;
            cp16(base + off, ws + off);
        }
        const char* xsrc = xfb + (size_t)c * 16384;
#pragma unroll
        for (int i = 0; i < 4; i++) {
            uint32_t off = (uint32_t)(t + i * 256) * 16;
            cp16(base + 81920 + off, xsrc + off);
        }
        cp_commit();
    };

    float acc[20][4];
#pragma unroll
    for (int nb = 0; nb < 20; nb++)
#pragma unroll
        for (int i = 0; i < 4; i++) acc[nb][i] = 0.f;

    load_chunk(0, 0);

    for (int c = 0; c < 4; c++) {
        const int st = c & 1;
        if (c + 1 < 4) {
            load_chunk(c + 1, st ^ 1);
            asm volatile("cp.async.wait_group 1;" ::: "memory");
        } else {
            asm volatile("cp.async.wait_group 0;" ::: "memory");
        }
        __syncthreads();

        const char* smW = dynsm + st * PJ_STAGE;
        const char* smX = smW + 81920;

#pragma unroll
        for (int ks = 0; ks < 4; ks++) {
            uint32_t ah[4], al[4];
            {
                uint4 u = *(const uint4*)(smX + (((strip * 4 + ks) * 2 + 0) * 32 + lane) * 16);
                ah[0] = u.x; ah[1] = u.y; ah[2] = u.z; ah[3] = u.w;
                uint4 v = *(const uint4*)(smX + (((strip * 4 + ks) * 2 + 1) * 32 + lane) * 16);
                al[0] = v.x; al[1] = v.y; al[2] = v.z; al[3] = v.w;
            }
#pragma unroll
            for (int nb = 0; nb < 20; nb++) {
                const char* wbase = smW + ((((half * 20 + nb) * 4 + ks) * 2) * 32 + lane) * 8;
                uint2 bh = *(const uint2*)wbase;
                uint2 bl = *(const uint2*)(wbase + 256);
                mma16816(acc[nb], ah, (const uint32_t*)&bh);
                mma16816(acc[nb], al, (const uint32_t*)&bh);
                mma16816(acc[nb], ah, (const uint32_t*)&bl);
            }
        }
        __syncthreads();
    }

    float* so = (float*)dynsm;
#pragma unroll
    for (int nb = 0; nb < 20; nb++) {
        int m = half * 160 + nb * 8 + t4 * 2;
        int px0 = strip * 16 + g, px1 = px0 + 8;
        so[px0 * OSTR + m]     = acc[nb][0];
        so[px0 * OSTR + m + 1] = acc[nb][1];
        so[px1 * OSTR + m]     = acc[nb][2];
        so[px1 * OSTR + m + 1] = acc[nb][3];
    }
    __syncthreads();

    const float L2E = 1.4426950408889634f;
    char* qf = g_Qf + ((size_t)b * (N_ / 16) + tile * 4) * 2048;
    char* kf = g_Kf + ((size_t)b * 64 + tile) * 8192;
    char* vf = g_Vf + ((size_t)b * 64 + tile) * 32768;

#pragma unroll
    for (int it = 0; it < 8; it++) {
        int w2 = t + it * 256;
        int wt = w2 >> 9, rem = w2 & 511;
        int ks = rem >> 8, hl = (rem >> 7) & 1, lane2 = (rem >> 2) & 31, reg = rem & 3;
        int r = (lane2 >> 2) + (reg & 1) * 8;
        int p2 = wt * 16 + r;
        int d = ks * 16 + ((reg >> 1) & 1) * 8 + (lane2 & 3) * 2;
        float v0 = (so[p2 * OSTR + d] + bq[d]) * L2E;
        float v1 = (so[p2 * OSTR + d + 1] + bq[d + 1]) * L2E;
        *(uint32_t*)(qf + (size_t)w2 * 4) = split_word(v0, v1, hl);
    }
#pragma unroll
    for (int it = 0; it < 8; it++) {
        int w2 = t + it * 256;
        int nt = w2 >> 8, ks = (w2 >> 7) & 1, hl = (w2 >> 6) & 1, lane2 = (w2 >> 1) & 31, reg = w2 & 1;
        int j = nt * 8 + (lane2 >> 2);
        int d = ks * 16 + reg * 8 + (lane2 & 3) * 2;
        float v0 = so[j * OSTR + 32 + d] + bk[d];
        float v1 = so[j * OSTR + 33 + d] + bk[d + 1];
        *(uint32_t*)(kf + (size_t)w2 * 4) = split_word(v0, v1, hl);
    }
#pragma unroll
    for (int it = 0; it < 32; it++) {
        int w2 = t + it * 256;
        int ks = w2 >> 11, ct = (w2 >> 6) & 31, lane2 = (w2 >> 1) & 31, reg = w2 & 1;
        int c = ct * 8 + (lane2 >> 2);
        int j = ks * 16 + reg * 8 + (lane2 & 3) * 2;
        float bb = bv[c];
        float v0 = so[j * OSTR + 64 + c] + bb;
        float v1 = so[(j + 1) * OSTR + 64 + c] + bb;
        *(uint32_t*)(vf + (size_t)w2 * 4) = h2(v0, v1);
    }
}

// ============ attn: 128-key tiles, amortized softmax ============
// stage = 16KB K (2 granules) + 64KB V (2 granules) = 80KB, double-buffered
constexpr int STAGE = 81920;
constexpr int ATTN_SMEM = 2 * STAGE;   // 163840

__global__ void __launch_bounds__(256, 1) attn_kernel(float* __restrict__ out)
{
    extern __shared__ __align__(16) char dynsm[];
    const uint32_t sb = smem_u32(dynsm);
    const int t = threadIdx.x, w = t >> 5, lane = t & 31;
    const int b = blockIdx.y;
    const int g = lane >> 2, t4 = lane & 3;
    const int wt = blockIdx.x * 8 + w;

    uint32_t qA[2][2][4];
    {
        const char* qf = g_Qf + ((size_t)b * (N_ / 16) + wt) * 2048;
#pragma unroll
        for (int ks = 0; ks < 2; ks++)
#pragma unroll
            for (int hl = 0; hl < 2; hl++) {
                uint4 u = *(const uint4*)(qf + ((ks * 2 + hl) * 32 + lane) * 16);
                qA[ks][hl][0] = u.x; qA[ks][hl][1] = u.y;
                qA[ks][hl][2] = u.z; qA[ks][hl][3] = u.w;
            }
    }

    float O[32][4];
#pragma unroll
    for (int ct = 0; ct < 32; ct++)
#pragma unroll
        for (int i = 0; i < 4; i++) O[ct][i] = 0.f;
    float m0 = -1e30f, m1 = -1e30f;
    float l0 = 0.f, l1 = 0.f;         // per-thread partial sums

    const char* kfb = g_Kf + (size_t)b * 64 * 8192;
    const char* vfb = g_Vf + (size_t)b * 64 * 32768;

    // 128-key tile: two consecutive 64-key granules (contiguous in gmem)
    auto load_tile = [&](int tt, int st) {
        const char* kf = kfb + (size_t)tt * 16384;
        const char* vf = vfb + (size_t)tt * 65536;
        uint32_t base = sb + st * STAGE;
#pragma unroll
        for (int i = 0; i < 4; i++) {
            uint32_t off = (uint32_t)(t + i * 256) * 16;
            cp16(base + off, kf + off);
        }
#pragma unroll
        for (int i = 0; i < 16; i++) {
            uint32_t off = (uint32_t)(t + i * 256) * 16;
            cp16(base + 16384 + off, vf + off);
        }
        cp_commit();
    };

    load_tile(0, 0);

    for (int tt = 0; tt < 32; tt++) {
        const int st = tt & 1;
        if (tt + 1 < 32) {
            load_tile(tt + 1, st ^ 1);
            asm volatile("cp.async.wait_group 1;" ::: "memory");
        } else {
            asm volatile("cp.async.wait_group 0;" ::: "memory");
        }
        __syncthreads();

        const char* smKb = dynsm + st * STAGE;
        const char* smV  = smKb + 16384;

        uint32_t pf[2][8][2];
        float corrT0 = 1.f, corrT1 = 1.f;

#pragma unroll
        for (int half = 0; half < 2; half++) {
            const char* smK = smKb + half * 8192;

            // ---- QK^T for 64 keys (split-fp16, 3 products) ----
            float sA[8][4];
#pragma unroll
            for (int nt = 0; nt < 8; nt++)
#pragma unroll
                for (int i = 0; i < 4; i++) sA[nt][i] = 0.f;

#pragma unroll
            for (int ks = 0; ks < 2; ks++) {
                uint2 bf[8][2];
#pragma unroll
                for (int nt = 0; nt < 8; nt++)
#pragma unroll
                    for (int hb = 0; hb < 2; hb++)
                        bf[nt][hb] = *(const uint2*)(smK + (((nt * 2 + ks) * 2 + hb) * 32 + lane) * 8);
#pragma unroll
                for (int nt = 0; nt < 8; nt++)
                    mma16816(sA[nt], qA[ks][0], (const uint32_t*)&bf[nt][0]);
#pragma unroll
                for (int nt = 0; nt < 8; nt++)
                    mma16816(sA[nt], qA[ks][0], (const uint32_t*)&bf[nt][1]);
#pragma unroll
                for (int nt = 0; nt < 8; nt++)
                    mma16816(sA[nt], qA[ks][1], (const uint32_t*)&bf[nt][0]);
            }

            // ---- block max (shfl over 4-lane group) ----
            float mx0 = sA[0][0], mx1 = sA[0][2];
#pragma unroll
            for (int nt = 0; nt < 8; nt++) {
                mx0 = fmaxf(mx0, fmaxf(sA[nt][0], sA[nt][1]));
                mx1 = fmaxf(mx1, fmaxf(sA[nt][2], sA[nt][3]));
            }
            mx0 = fmaxf(mx0, __shfl_xor_sync(0xffffffffu, mx0, 1, 4));
            mx0 = fmaxf(mx0, __shfl_xor_sync(0xffffffffu, mx0, 2, 4));
            mx1 = fmaxf(mx1, __shfl_xor_sync(0xffffffffu, mx1, 1, 4));
            mx1 = fmaxf(mx1, __shfl_xor_sync(0xffffffffu, mx1, 2, 4));
            float mn0 = fmaxf(m0, mx0), mn1 = fmaxf(m1, mx1);
            float corr0 = (mn0 == m0) ? 1.f : ex2a(m0 - mn0);
            float corr1 = (mn1 == m1) ? 1.f : ex2a(m1 - mn1);
            m0 = mn0; m1 = mn1;
            corrT0 *= corr0; corrT1 *= corr1;

            // rescale half-0 P fragments if max moved during half 1
            if (half == 1 && !__all_sync(0xffffffffu, (corr0 == 1.f) & (corr1 == 1.f))) {
                uint32_t c0h = h2(corr0, corr0), c1h = h2(corr1, corr1);
#pragma unroll
                for (int nt = 0; nt < 8; nt++) {
                    pf[0][nt][0] = hmul2(pf[0][nt][0], c0h);
                    pf[0][nt][1] = hmul2(pf[0][nt][1], c1h);
                }
            }

            // ---- exp + per-thread partial l ----
            float ls0 = 0.f, ls1 = 0.f;
#pragma unroll
            for (int nt = 0; nt < 8; nt++) {
                float p0 = ex2a(sA[nt][0] - mn0);
                float p1 = ex2a(sA[nt][1] - mn0);
                float p2 = ex2a(sA[nt][2] - mn1);
                float p3 = ex2a(sA[nt][3] - mn1);
                ls0 += p0 + p1; ls1 += p2 + p3;
                pf[half][nt][0] = h2(p0, p1);
                pf[half][nt][1] = h2(p2, p3);
            }
            l0 = l0 * corr0 + ls0;
            l1 = l1 * corr1 + ls1;
        }

        // ---- rescale O once per 128 keys (skip when stable) ----
        if (!__all_sync(0xffffffffu, (corrT0 == 1.f) & (corrT1 == 1.f))) {
#pragma unroll
            for (int ct = 0; ct < 32; ct++) {
                O[ct][0] *= corrT0; O[ct][1] *= corrT0;
                O[ct][2] *= corrT1; O[ct][3] *= corrT1;
            }
        }

        // ---- P V over 128 keys ----
#pragma unroll
        for (int vt = 0; vt < 2; vt++) {
            const char* vg = smV + vt * 32768;
#pragma unroll
            for (int ks = 0; ks < 4; ks++) {
                uint32_t a[4] = { pf[vt][2 * ks][0], pf[vt][2 * ks][1],
                                  pf[vt][2 * ks + 1][0], pf[vt][2 * ks + 1][1] };
#pragma unroll
                for (int ct = 0; ct < 32; ct++) {
                    uint2 vb = *(const uint2*)(vg + ((ks * 32 + ct) * 32 + lane) * 8);
                    mma16816(O[ct], a, (const uint32_t*)&vb);
                }
            }
        }
        __syncthreads();
    }

    // ---- final l reduction across the 4-lane group ----
    l0 += __shfl_xor_sync(0xffffffffu, l0, 1, 4);
    l0 += __shfl_xor_sync(0xffffffffu, l0, 2, 4);
    l1 += __shfl_xor_sync(0xffffffffu, l1, 1, 4);
    l1 += __shfl_xor_sync(0xffffffffu, l1, 2, 4);

    const float inv0 = 1.f / l0, inv1 = 1.f / l1;
    const int nr0 = blockIdx.x * 128 + w * 16 + g;
    const int nr1 = nr0 + 8;
    float* ob = out + (size_t)b * C_ * N_;
#pragma unroll
    for (int ct = 0; ct < 32; ct++) {
        int c = ct * 8 + t4 * 2;
        ob[(size_t)c * N_ + nr0]       = O[ct][0] * inv0;
        ob[(size_t)(c + 1) * N_ + nr0] = O[ct][1] * inv0;
        ob[(size_t)c * N_ + nr1]       = O[ct][2] * inv1;
        ob[(size_t)(c + 1) * N_ + nr1] = O[ct][3] * inv1;
    }
}

// ============ launch ============
extern "C" void kernel_launch(void* const* d_in, const int* in_sizes, int n_in,
                              void* d_out, int out_size)
{
    const float* x  = (const float*)d_in[0];
    const float* Wq = (const float*)d_in[1];
    const float* bq = (const float*)d_in[2];
    const float* Wk = (const float*)d_in[3];
    const float* bk = (const float*)d_in[4];
    const float* Wv = (const float*)d_in[5];
    const float* bv = (const float*)d_in[6];
    float* out = (float*)d_out;

    cudaFuncSetAttribute(xprep_kernel, cudaFuncAttributeMaxDynamicSharedMemorySize, XP_SMEM);
    cudaFuncSetAttribute(proj_kernel,  cudaFuncAttributeMaxDynamicSharedMemorySize, PJ_SMEM);
    cudaFuncSetAttribute(attn_kernel,  cudaFuncAttributeMaxDynamicSharedMemorySize, ATTN_SMEM);

    wprep_kernel<<<320, 256>>>(Wq, Wk, Wv);
    xprep_kernel<<<dim3(64, B_), 256, XP_SMEM>>>(x);
    proj_kernel<<<dim3(64, B_), 256, PJ_SMEM>>>(bq, bk, bv);
    attn_kernel<<<dim3(N_ / 128, B_), 256, ATTN_SMEM>>>(out);
}